// round 6
// baseline (speedup 1.0000x reference)
#include <cuda_runtime.h>
#include <math.h>

#define BB 512
#define TT 64
#define HH 256
#define ZZ 64
#define PP 10000
#define NTOK (BB*TT)

// ------------------- device scratch (no allocs allowed) -------------------
__device__ float g_h0[BB*HH];              // elu(z@Winit^T+b): initial hidden, both layers
__device__ float g_gx0[3*HH];              // layer-0 input gates (constant over b,t)
__device__ float g_y0[NTOK*HH];            // layer-0 outputs / hidden trajectory
__device__ float g_gx1[(size_t)NTOK*3*HH]; // layer-1 input gates (per token)
__device__ float g_y1[NTOK*HH];            // layer-1 outputs
__device__ float g_act[NTOK*HH];           // post LayerNorm+ELU activations
__device__ float g_WhhT0[HH*3*HH];         // Whh0^T -> [K=256][768]
__device__ float g_WhhT1[HH*3*HH];

// ------------------------------ init kernels ------------------------------
__global__ void k_init_h0(const float* __restrict__ z, const float* __restrict__ Wi,
                          const float* __restrict__ bi){
    __shared__ float zs[ZZ];
    int b = blockIdx.x, h = threadIdx.x;
    if (h < ZZ) zs[h] = z[b*ZZ + h];
    __syncthreads();
    float acc = bi[h];
    #pragma unroll 8
    for (int k = 0; k < ZZ; k++) acc += zs[k] * Wi[h*ZZ + k];
    g_h0[b*HH + h] = acc > 0.f ? acc : expm1f(acc);
}

__global__ void k_gx0(const float* __restrict__ emb, const float* __restrict__ Wih0,
                      const float* __restrict__ bih0){
    __shared__ float es[HH];
    int i = blockIdx.x*256 + threadIdx.x;     // grid=3 -> i in [0,768)
    es[threadIdx.x] = emb[threadIdx.x];
    __syncthreads();
    float acc = bih0[i];
    #pragma unroll 8
    for (int k = 0; k < HH; k++) acc += es[k] * Wih0[i*HH + k];
    g_gx0[i] = acc;
}

// transpose [768][256] -> [256][768] into g_WhhT0 / g_WhhT1 (sel)
__global__ void k_transpose(const float* __restrict__ in, int sel){
    float* out = sel ? g_WhhT1 : g_WhhT0;
    __shared__ float t[32][33];
    int c0 = blockIdx.x*32;   // k (256) dim
    int r0 = blockIdx.y*32;   // 768 dim
    int tx = threadIdx.x, ty = threadIdx.y;   // 32x8
    #pragma unroll
    for (int i = 0; i < 32; i += 8)
        t[ty+i][tx] = in[(r0+ty+i)*HH + c0+tx];
    __syncthreads();
    #pragma unroll
    for (int i = 0; i < 32; i += 8)
        out[(size_t)(c0+ty+i)*768 + r0+tx] = t[tx][ty+i];
}

// ------------------------------ GRU step ----------------------------------
// One step of layer `layer` at time `t`.
//   layer 0: h_src = (t==0? g_h0 : g_y0[t-1]), gx broadcast from g_gx0, dst g_y0[t]
//   layer 1: h_src = (t==0? g_h0 : g_y1[t-1]), gx = g_gx1[b][t],       dst g_y1[t]
// Grid (4,32): blockIdx.x -> 64-wide j slice, blockIdx.y -> 16 batch rows.
__global__ void __launch_bounds__(256) k_gru_step(
    int layer, int t, const float* __restrict__ bhh)
{
    const float* WhhT = layer ? g_WhhT1 : g_WhhT0;
    float* ybuf       = layer ? g_y1    : g_y0;
    const float* hsrc; int src_bstride;
    if (t == 0){ hsrc = g_h0;                      src_bstride = HH;    }
    else       { hsrc = ybuf + (size_t)(t-1)*HH;   src_bstride = TT*HH; }
    const float* gx; size_t gx_bstride;
    if (layer){ gx = g_gx1 + (size_t)t*3*HH; gx_bstride = (size_t)TT*3*HH; }
    else      { gx = g_gx0;                  gx_bstride = 0; }
    float* dst = ybuf + (size_t)t*HH;
    const int dst_bstride = TT*HH;

    __shared__ float As[HH][20];      // h_prev transposed [k][row], pad for f4 align
    __shared__ float Bs[32][192];     // Whh^T chunk [k][gate*64+j]
    int tid = threadIdx.x;
    int j  = tid & 63;
    int rg = tid >> 6;
    int b0 = blockIdx.y * 16;
    int j0 = blockIdx.x * 64;

    // load 16 rows x 256 of h_prev, transposed (coalesced gmem reads)
    #pragma unroll 4
    for (int r = 0; r < 16; r++)
        As[tid][r] = hsrc[(size_t)(b0 + r)*src_bstride + tid];

    float ar[4] = {0,0,0,0}, az[4] = {0,0,0,0}, an[4] = {0,0,0,0};
    for (int k0 = 0; k0 < HH; k0 += 32){
        __syncthreads();   // protects previous Bs use + first-iter As completion
        #pragma unroll
        for (int l = 0; l < 6; l++){
            int fi = l*256 + tid;           // float4 index 0..1535
            int kk = fi / 48, c4 = fi % 48;
            int gj = c4*4, g = gj >> 6, jj = gj & 63;
            *(float4*)&Bs[kk][gj] =
                *(const float4*)&WhhT[(size_t)(k0+kk)*768 + g*HH + j0 + jj];
        }
        __syncthreads();
        #pragma unroll
        for (int kk = 0; kk < 32; kk++){
            float4 a = *(const float4*)&As[k0+kk][rg*4];
            float br = Bs[kk][j], bz = Bs[kk][64+j], bn = Bs[kk][128+j];
            ar[0]+=a.x*br; ar[1]+=a.y*br; ar[2]+=a.z*br; ar[3]+=a.w*br;
            az[0]+=a.x*bz; az[1]+=a.y*bz; az[2]+=a.z*bz; az[3]+=a.w*bz;
            an[0]+=a.x*bn; an[1]+=a.y*bn; an[2]+=a.z*bn; an[3]+=a.w*bn;
        }
    }

    int jc = j0 + j;
    float bhr = bhh[jc], bhz = bhh[HH+jc], bhn = bhh[2*HH+jc];
    #pragma unroll
    for (int i = 0; i < 4; i++){
        int b = b0 + rg*4 + i;
        const float* gxp = gx + (size_t)b * gx_bstride;
        float xr = gxp[jc], xz = gxp[HH+jc], xn = gxp[2*HH+jc];
        float r_ = 1.f/(1.f + expf(-(xr + ar[i] + bhr)));
        float u_ = 1.f/(1.f + expf(-(xz + az[i] + bhz)));
        float n_ = tanhf(xn + r_*(an[i] + bhn));
        float hold = As[jc][rg*4 + i];
        dst[(size_t)b*dst_bstride + jc] = (1.f - u_)*n_ + u_*hold;
    }
}

// ------------------------- generic SGEMM + bias ----------------------------
// C[M,N] = A[M,K=256] @ B[N,K]^T + bias[N]. Tile 128x128, Ktile 32, 8x8/thread.
// Asel: 0 -> g_y0, 1 -> g_act.  Csel: 0 -> Cout arg (d_out), 1 -> g_gx1.
__global__ void __launch_bounds__(256) k_sgemm_bias(
    int Asel, const float* __restrict__ Bm,
    const float* __restrict__ bias, float* Cout, int Csel, int N)
{
    const float* A = Asel ? g_act : g_y0;
    float* C = Csel ? g_gx1 : Cout;
    const int K = 256;
    __shared__ float As[32][132];
    __shared__ float Bs[32][132];
    int m0 = blockIdx.y * 128, n0 = blockIdx.x * 128;
    int tid = threadIdx.x;
    int tx = tid & 15, ty = tid >> 4;
    float acc[8][8];
    #pragma unroll
    for (int i = 0; i < 8; i++)
        #pragma unroll
        for (int jj = 0; jj < 8; jj++) acc[i][jj] = 0.f;

    for (int k0 = 0; k0 < K; k0 += 32){
        #pragma unroll
        for (int l = 0; l < 4; l++){
            int fi = l*256 + tid;      // f4 index; 8 f4 per row
            int r = fi >> 3, c4 = fi & 7;
            float4 v = *(const float4*)&A[(size_t)(m0+r)*K + k0 + c4*4];
            As[c4*4+0][r]=v.x; As[c4*4+1][r]=v.y; As[c4*4+2][r]=v.z; As[c4*4+3][r]=v.w;
        }
        #pragma unroll
        for (int l = 0; l < 4; l++){
            int fi = l*256 + tid;
            int r = fi >> 3, c4 = fi & 7;
            int n = n0 + r;
            float4 v = make_float4(0.f,0.f,0.f,0.f);
            if (n < N) v = *(const float4*)&Bm[(size_t)n*K + k0 + c4*4];
            Bs[c4*4+0][r]=v.x; Bs[c4*4+1][r]=v.y; Bs[c4*4+2][r]=v.z; Bs[c4*4+3][r]=v.w;
        }
        __syncthreads();
        #pragma unroll
        for (int k = 0; k < 32; k++){
            float a[8], bb[8];
            *(float4*)&a[0]  = *(const float4*)&As[k][ty*4];
            *(float4*)&a[4]  = *(const float4*)&As[k][64 + ty*4];
            *(float4*)&bb[0] = *(const float4*)&Bs[k][tx*4];
            *(float4*)&bb[4] = *(const float4*)&Bs[k][64 + tx*4];
            #pragma unroll
            for (int i = 0; i < 8; i++)
                #pragma unroll
                for (int jj = 0; jj < 8; jj++) acc[i][jj] += a[i]*bb[jj];
        }
        __syncthreads();
    }

    #pragma unroll
    for (int i = 0; i < 8; i++){
        int row = m0 + ((i < 4) ? (ty*4 + i) : (64 + ty*4 + i - 4));
        #pragma unroll
        for (int q = 0; q < 2; q++){
            int col = n0 + (q ? 64 + tx*4 : tx*4);
            if (col < N){
                float4 o;
                o.x = acc[i][q*4+0] + bias[col+0];
                o.y = acc[i][q*4+1] + bias[col+1];
                o.z = acc[i][q*4+2] + bias[col+2];
                o.w = acc[i][q*4+3] + bias[col+3];
                *(float4*)&C[(size_t)row*N + col] = o;
            }
        }
    }
}

// --------------------------- LayerNorm + ELU -------------------------------
__global__ void k_ln_elu(const float* __restrict__ g, const float* __restrict__ bt){
    __shared__ float red[8];
    int tok = blockIdx.x, tid = threadIdx.x;
    float v = g_y1[(size_t)tok*HH + tid];

    float s = v;
    #pragma unroll
    for (int o = 16; o; o >>= 1) s += __shfl_xor_sync(~0u, s, o);
    if ((tid & 31) == 0) red[tid >> 5] = s;
    __syncthreads();
    if (tid < 32){
        float t = (tid < 8) ? red[tid] : 0.f;
        #pragma unroll
        for (int o = 4; o; o >>= 1) t += __shfl_xor_sync(~0u, t, o);
        if (tid == 0) red[0] = t;
    }
    __syncthreads();
    float mu = red[0] * (1.f/HH);
    __syncthreads();

    float d = v - mu;
    float sq = d*d;
    #pragma unroll
    for (int o = 16; o; o >>= 1) sq += __shfl_xor_sync(~0u, sq, o);
    if ((tid & 31) == 0) red[tid >> 5] = sq;
    __syncthreads();
    if (tid < 32){
        float t = (tid < 8) ? red[tid] : 0.f;
        #pragma unroll
        for (int o = 4; o; o >>= 1) t += __shfl_xor_sync(~0u, t, o);
        if (tid == 0) red[0] = t;
    }
    __syncthreads();
    float var = red[0] * (1.f/HH);

    float o = d * rsqrtf(var + 1e-5f) * g[tid] + bt[tid];
    o = o > 0.f ? o : expm1f(o);
    g_act[(size_t)tok*HH + tid] = o;
}

// ------------------------------ launcher -----------------------------------
extern "C" void kernel_launch(void* const* d_in, const int* in_sizes, int n_in,
                              void* d_out, int out_size){
    const float* z     = (const float*)d_in[0];
    const float* Winit = (const float*)d_in[1];
    const float* binit = (const float*)d_in[2];
    const float* emb   = (const float*)d_in[3];
    const float* Wih0  = (const float*)d_in[4];
    const float* Whh0  = (const float*)d_in[5];
    const float* bih0  = (const float*)d_in[6];
    const float* bhh0  = (const float*)d_in[7];
    const float* Wih1  = (const float*)d_in[8];
    const float* Whh1  = (const float*)d_in[9];
    const float* bih1  = (const float*)d_in[10];
    const float* bhh1  = (const float*)d_in[11];
    const float* lng   = (const float*)d_in[12];
    const float* lnb   = (const float*)d_in[13];
    const float* Wout  = (const float*)d_in[14];
    const float* bout  = (const float*)d_in[15];
    float* out = (float*)d_out;

    k_transpose<<<dim3(8,24), dim3(32,8)>>>(Whh0, 0);
    k_transpose<<<dim3(8,24), dim3(32,8)>>>(Whh1, 1);
    k_init_h0<<<BB, HH>>>(z, Winit, binit);
    k_gx0<<<3, HH>>>(emb, Wih0, bih0);

    // GRU layer 0: input gates constant (g_gx0), hidden trajectory -> g_y0
    for (int t = 0; t < TT; t++)
        k_gru_step<<<dim3(4,32), 256>>>(0, t, bhh0);

    // input gates for layer 1: gx1 = y0 @ Wih1^T + bih1  (32768 x 768, K=256)
    k_sgemm_bias<<<dim3(6,256), 256>>>(0, Wih1, bih1, nullptr, 1, 3*HH);

    // GRU layer 1
    for (int t = 0; t < TT; t++)
        k_gru_step<<<dim3(4,32), 256>>>(1, t, bhh1);

    k_ln_elu<<<NTOK, HH>>>(lng, lnb);

    // logits = act @ Wout^T + bout  (32768 x 10000, K=256)
    k_sgemm_bias<<<dim3(79,256), 256>>>(1, Wout, bout, out, 0, PP);
}

// round 10
// speedup vs baseline: 1.5654x; 1.5654x over previous
#include <cuda_runtime.h>
#include <cuda_bf16.h>
#include <math.h>
#include <stdint.h>

#define BB 512
#define TT 64
#define HH 256
#define ZZ 64
#define PP 10000
#define NTOK (BB*TT)
#define NPAD 10240          // PP padded to 128-col N tiles
#define KSP 768             // split-K: [hi|lo|hi] x [hi|hi|lo]

// ------------------- device scratch (no allocs allowed) -------------------
__device__ float g_h0[BB*HH];
__device__ float g_gx0[3*HH];
__device__ float g_y0[NTOK*HH];
__device__ float g_gx1[(size_t)NTOK*3*HH];
__device__ float g_y1[NTOK*HH];
__device__ float g_act[NTOK*HH];
__device__ float g_WhhT0[HH*3*HH];
__device__ float g_WhhT1[HH*3*HH];
__device__ __nv_bfloat16 g_A2[(size_t)NTOK*KSP];   // split activations [hi|lo|hi]
__device__ __nv_bfloat16 g_B2[(size_t)NPAD*KSP];   // split weights     [hi|hi|lo]

// ----------------------------- helpers ------------------------------------
__device__ __forceinline__ uint32_t smem_u32(const void* p){
    uint32_t a;
    asm("{ .reg .u64 t; cvta.to.shared.u64 t, %1; cvt.u32.u64 %0, t; }" : "=r"(a) : "l"(p));
    return a;
}
#define CP_ASYNC16(sa, gp) \
    asm volatile("cp.async.cg.shared.global [%0], [%1], 16;" :: "r"(sa), "l"(gp) : "memory")
#define CP_COMMIT() asm volatile("cp.async.commit_group;" ::: "memory")
#define LDSM_X4(r, a) \
    asm volatile("ldmatrix.sync.aligned.m8n8.x4.shared.b16 {%0,%1,%2,%3}, [%4];" \
        : "=r"((r)[0]),"=r"((r)[1]),"=r"((r)[2]),"=r"((r)[3]) : "r"(a))
#define LDSM_X2(r, a) \
    asm volatile("ldmatrix.sync.aligned.m8n8.x2.shared.b16 {%0,%1}, [%2];" \
        : "=r"((r)[0]),"=r"((r)[1]) : "r"(a))
#define MMA16816(c, a, b) \
    asm volatile("mma.sync.aligned.m16n8k16.row.col.f32.bf16.bf16.f32 " \
        "{%0,%1,%2,%3}, {%4,%5,%6,%7}, {%8,%9}, {%0,%1,%2,%3};" \
        : "+f"((c)[0]),"+f"((c)[1]),"+f"((c)[2]),"+f"((c)[3]) \
        : "r"((a)[0]),"r"((a)[1]),"r"((a)[2]),"r"((a)[3]), "r"((b)[0]),"r"((b)[1]))

// ------------------------------ init kernels ------------------------------
__global__ void k_init_h0(const float* __restrict__ z, const float* __restrict__ Wi,
                          const float* __restrict__ bi){
    __shared__ float zs[ZZ];
    int b = blockIdx.x, h = threadIdx.x;
    if (h < ZZ) zs[h] = z[b*ZZ + h];
    __syncthreads();
    float acc = bi[h];
    #pragma unroll 8
    for (int k = 0; k < ZZ; k++) acc += zs[k] * Wi[h*ZZ + k];
    g_h0[b*HH + h] = acc > 0.f ? acc : expm1f(acc);
}

__global__ void k_gx0(const float* __restrict__ emb, const float* __restrict__ Wih0,
                      const float* __restrict__ bih0){
    __shared__ float es[HH];
    int i = blockIdx.x*256 + threadIdx.x;
    es[threadIdx.x] = emb[threadIdx.x];
    __syncthreads();
    float acc = bih0[i];
    #pragma unroll 8
    for (int k = 0; k < HH; k++) acc += es[k] * Wih0[i*HH + k];
    g_gx0[i] = acc;
}

__global__ void k_transpose(const float* __restrict__ in, int sel){
    float* out = sel ? g_WhhT1 : g_WhhT0;
    __shared__ float t[32][33];
    int c0 = blockIdx.x*32, r0 = blockIdx.y*32;
    int tx = threadIdx.x, ty = threadIdx.y;
    #pragma unroll
    for (int i = 0; i < 32; i += 8)
        t[ty+i][tx] = in[(r0+ty+i)*HH + c0+tx];
    __syncthreads();
    #pragma unroll
    for (int i = 0; i < 32; i += 8)
        out[(size_t)(c0+ty+i)*768 + r0+tx] = t[tx][ty+i];
}

// ------------------- bf16 split conversions -------------------------------
__global__ void k_splitA(int sel){   // src fp32 [NTOK][256] -> g_A2 [hi|lo|hi]
    const float* src = sel ? g_act : g_y0;
    size_t idx = (size_t)blockIdx.x*256 + threadIdx.x;   // over NTOK*64
    size_t m = idx >> 6; int q = (int)(idx & 63);
    float4 v = *(const float4*)&src[m*HH + q*4];
    __nv_bfloat16 h0=__float2bfloat16(v.x), h1=__float2bfloat16(v.y),
                  h2=__float2bfloat16(v.z), h3=__float2bfloat16(v.w);
    __nv_bfloat16 l0=__float2bfloat16(v.x-__bfloat162float(h0)),
                  l1=__float2bfloat16(v.y-__bfloat162float(h1)),
                  l2=__float2bfloat16(v.z-__bfloat162float(h2)),
                  l3=__float2bfloat16(v.w-__bfloat162float(h3));
    __nv_bfloat162 hp0, hp1, lp0, lp1;
    hp0.x=h0; hp0.y=h1; hp1.x=h2; hp1.y=h3;
    lp0.x=l0; lp0.y=l1; lp1.x=l2; lp1.y=l3;
    __nv_bfloat16* base = g_A2 + m*KSP + q*4;
    *(__nv_bfloat162*)(base+0)     = hp0; *(__nv_bfloat162*)(base+2)     = hp1;
    *(__nv_bfloat162*)(base+256)   = lp0; *(__nv_bfloat162*)(base+258)   = lp1;
    *(__nv_bfloat162*)(base+512)   = hp0; *(__nv_bfloat162*)(base+514)   = hp1;
}

__global__ void k_splitB(const float* __restrict__ W, int rows){ // -> g_B2 [hi|hi|lo]
    size_t idx = (size_t)blockIdx.x*256 + threadIdx.x;   // over NPAD*64
    size_t n = idx >> 6; int q = (int)(idx & 63);
    float4 v = make_float4(0.f,0.f,0.f,0.f);
    if (n < (size_t)rows) v = *(const float4*)&W[n*HH + q*4];
    __nv_bfloat16 h0=__float2bfloat16(v.x), h1=__float2bfloat16(v.y),
                  h2=__float2bfloat16(v.z), h3=__float2bfloat16(v.w);
    __nv_bfloat16 l0=__float2bfloat16(v.x-__bfloat162float(h0)),
                  l1=__float2bfloat16(v.y-__bfloat162float(h1)),
                  l2=__float2bfloat16(v.z-__bfloat162float(h2)),
                  l3=__float2bfloat16(v.w-__bfloat162float(h3));
    __nv_bfloat162 hp0, hp1, lp0, lp1;
    hp0.x=h0; hp0.y=h1; hp1.x=h2; hp1.y=h3;
    lp0.x=l0; lp0.y=l1; lp1.x=l2; lp1.y=l3;
    __nv_bfloat16* base = g_B2 + n*KSP + q*4;
    *(__nv_bfloat162*)(base+0)     = hp0; *(__nv_bfloat162*)(base+2)     = hp1;
    *(__nv_bfloat162*)(base+256)   = hp0; *(__nv_bfloat162*)(base+258)   = hp1;
    *(__nv_bfloat162*)(base+512)   = lp0; *(__nv_bfloat162*)(base+514)   = lp1;
}

// ---------------- mma.sync GEMM: C[M,N] = A2 @ B2^T + bias -----------------
// CTA tile 128x128, K'=768 in 12 chunks of 64, cp.async double buffer.
// 8 warps in 2(M)x4(N); warp tile 64x32. grid=(ceil(N/128), NTOK/128).
#define CHK 64
#define STR 72                             // smem row stride (bf16)
#define ATS (128*STR*2)                    // one matrix tile bytes (18432)
#define STG (2*ATS)                        // stage (A+B) bytes
#define GSM (2*STG)                        // total dyn smem (73728)

__global__ void __launch_bounds__(256, 2) k_mma_gemm(
    const float* __restrict__ bias, float* Cout, int Csel, int N)
{
    extern __shared__ char smem[];
    float* C = Csel ? g_gx1 : Cout;
    const int tid = threadIdx.x;
    const int m0 = blockIdx.y * 128;
    const int n0 = blockIdx.x * 128;
    const __nv_bfloat16* Ag = g_A2 + (size_t)m0 * KSP;
    const __nv_bfloat16* Bg = g_B2 + (size_t)n0 * KSP;
    const uint32_t sb = smem_u32(smem);

    auto load_chunk = [&](int s, int kc){
        uint32_t base = sb + s*STG;
        #pragma unroll
        for (int l = 0; l < 4; l++){
            int fi = l*256 + tid, row = fi >> 3, c = fi & 7;
            CP_ASYNC16(base + (row*STR + c*8)*2,
                       (const void*)(Ag + (size_t)row*KSP + kc + c*8));
        }
        #pragma unroll
        for (int l = 0; l < 4; l++){
            int fi = l*256 + tid, row = fi >> 3, c = fi & 7;
            CP_ASYNC16(base + ATS + (row*STR + c*8)*2,
                       (const void*)(Bg + (size_t)row*KSP + kc + c*8));
        }
        CP_COMMIT();
    };

    load_chunk(0, 0);
    load_chunk(1, CHK);

    const int lane = tid & 31, w = tid >> 5;
    const int wy = w & 1, wx = w >> 1;          // 2 x 4 warp grid
    // ldmatrix source row/col offsets
    const int aRow = wy*64 + (lane & 7) + ((lane >> 3) & 1) * 8;  // + mf*16
    const int aK   = (lane >> 4) * 8;                             // + kk
    const int bRow = wx*32 + (lane & 7);                          // + nf*8
    const int bK   = ((lane >> 3) & 1) * 8;                       // + kk

    float acc[4][4][4];
    #pragma unroll
    for (int i = 0; i < 4; i++)
        #pragma unroll
        for (int jj = 0; jj < 4; jj++)
            #pragma unroll
            for (int q = 0; q < 4; q++) acc[i][jj][q] = 0.f;

    #pragma unroll 1
    for (int c = 0; c < 12; c++){
        int s = c & 1;
        if (c == 11) asm volatile("cp.async.wait_group 0;" ::: "memory");
        else         asm volatile("cp.async.wait_group 1;" ::: "memory");
        __syncthreads();
        uint32_t Ab = sb + s*STG;
        uint32_t Bb = Ab + ATS;
        #pragma unroll
        for (int kk = 0; kk < CHK; kk += 16){
            uint32_t a[4][4], b[4][2];
            #pragma unroll
            for (int mf = 0; mf < 4; mf++)
                LDSM_X4(a[mf], Ab + ((aRow + mf*16)*STR + kk + aK)*2);
            #pragma unroll
            for (int nf = 0; nf < 4; nf++)
                LDSM_X2(b[nf], Bb + ((bRow + nf*8)*STR + kk + bK)*2);
            #pragma unroll
            for (int mf = 0; mf < 4; mf++)
                #pragma unroll
                for (int nf = 0; nf < 4; nf++)
                    MMA16816(acc[mf][nf], a[mf], b[nf]);
        }
        __syncthreads();
        if (c + 2 < 12) load_chunk(s, (c+2)*CHK);
    }

    // ---- epilogue: each thread owns 2 rows x 2 cols per (mf,nf) fragment
    const int er = lane >> 2, ec = (lane & 3) * 2;
    #pragma unroll
    for (int mf = 0; mf < 4; mf++){
        size_t r0 = (size_t)(m0 + wy*64 + mf*16 + er);
        size_t r1 = r0 + 8;
        #pragma unroll
        for (int nf = 0; nf < 4; nf++){
            int col = n0 + wx*32 + nf*8 + ec;
            if (col < N){
                float2 b2 = *(const float2*)&bias[col];
                float2 o0, o1;
                o0.x = acc[mf][nf][0] + b2.x; o0.y = acc[mf][nf][1] + b2.y;
                o1.x = acc[mf][nf][2] + b2.x; o1.y = acc[mf][nf][3] + b2.y;
                *(float2*)&C[r0*(size_t)N + col] = o0;
                *(float2*)&C[r1*(size_t)N + col] = o1;
            }
        }
    }
}

// ------------------------------ GRU step ----------------------------------
__global__ void __launch_bounds__(256) k_gru_step(
    int layer, int t, const float* __restrict__ bhh)
{
    const float* WhhT = layer ? g_WhhT1 : g_WhhT0;
    float* ybuf       = layer ? g_y1    : g_y0;
    const float* hsrc; int src_bstride;
    if (t == 0){ hsrc = g_h0;                      src_bstride = HH;    }
    else       { hsrc = ybuf + (size_t)(t-1)*HH;   src_bstride = TT*HH; }
    const float* gx; size_t gx_bstride;
    if (layer){ gx = g_gx1 + (size_t)t*3*HH; gx_bstride = (size_t)TT*3*HH; }
    else      { gx = g_gx0;                  gx_bstride = 0; }
    float* dst = ybuf + (size_t)t*HH;
    const int dst_bstride = TT*HH;

    __shared__ float As[HH][20];
    __shared__ float Bs[32][192];
    int tid = threadIdx.x;
    int j  = tid & 63;
    int rg = tid >> 6;
    int b0 = blockIdx.y * 16;
    int j0 = blockIdx.x * 64;

    #pragma unroll 4
    for (int r = 0; r < 16; r++)
        As[tid][r] = hsrc[(size_t)(b0 + r)*src_bstride + tid];

    float ar[4] = {0,0,0,0}, az[4] = {0,0,0,0}, an[4] = {0,0,0,0};
    for (int k0 = 0; k0 < HH; k0 += 32){
        __syncthreads();
        #pragma unroll
        for (int l = 0; l < 6; l++){
            int fi = l*256 + tid;
            int kk = fi / 48, c4 = fi % 48;
            int gj = c4*4, g = gj >> 6, jj = gj & 63;
            *(float4*)&Bs[kk][gj] =
                *(const float4*)&WhhT[(size_t)(k0+kk)*768 + g*HH + j0 + jj];
        }
        __syncthreads();
        #pragma unroll
        for (int kk = 0; kk < 32; kk++){
            float4 a = *(const float4*)&As[k0+kk][rg*4];
            float br = Bs[kk][j], bz = Bs[kk][64+j], bn = Bs[kk][128+j];
            ar[0]+=a.x*br; ar[1]+=a.y*br; ar[2]+=a.z*br; ar[3]+=a.w*br;
            az[0]+=a.x*bz; az[1]+=a.y*bz; az[2]+=a.z*bz; az[3]+=a.w*bz;
            an[0]+=a.x*bn; an[1]+=a.y*bn; an[2]+=a.z*bn; an[3]+=a.w*bn;
        }
    }

    int jc = j0 + j;
    float bhr = bhh[jc], bhz = bhh[HH+jc], bhn = bhh[2*HH+jc];
    #pragma unroll
    for (int i = 0; i < 4; i++){
        int b = b0 + rg*4 + i;
        const float* gxp = gx + (size_t)b * gx_bstride;
        float xr = gxp[jc], xz = gxp[HH+jc], xn = gxp[2*HH+jc];
        float r_ = 1.f/(1.f + expf(-(xr + ar[i] + bhr)));
        float u_ = 1.f/(1.f + expf(-(xz + az[i] + bhz)));
        float n_ = tanhf(xn + r_*(an[i] + bhn));
        float hold = As[jc][rg*4 + i];
        dst[(size_t)b*dst_bstride + jc] = (1.f - u_)*n_ + u_*hold;
    }
}

// --------------------------- LayerNorm + ELU -------------------------------
__global__ void k_ln_elu(const float* __restrict__ g, const float* __restrict__ bt){
    __shared__ float red[8];
    int tok = blockIdx.x, tid = threadIdx.x;
    float v = g_y1[(size_t)tok*HH + tid];

    float s = v;
    #pragma unroll
    for (int o = 16; o; o >>= 1) s += __shfl_xor_sync(~0u, s, o);
    if ((tid & 31) == 0) red[tid >> 5] = s;
    __syncthreads();
    if (tid < 32){
        float t = (tid < 8) ? red[tid] : 0.f;
        #pragma unroll
        for (int o = 4; o; o >>= 1) t += __shfl_xor_sync(~0u, t, o);
        if (tid == 0) red[0] = t;
    }
    __syncthreads();
    float mu = red[0] * (1.f/HH);
    __syncthreads();

    float d = v - mu;
    float sq = d*d;
    #pragma unroll
    for (int o = 16; o; o >>= 1) sq += __shfl_xor_sync(~0u, sq, o);
    if ((tid & 31) == 0) red[tid >> 5] = sq;
    __syncthreads();
    if (tid < 32){
        float t = (tid < 8) ? red[tid] : 0.f;
        #pragma unroll
        for (int o = 4; o; o >>= 1) t += __shfl_xor_sync(~0u, t, o);
        if (tid == 0) red[0] = t;
    }
    __syncthreads();
    float var = red[0] * (1.f/HH);

    float o = d * rsqrtf(var + 1e-5f) * g[tid] + bt[tid];
    o = o > 0.f ? o : expm1f(o);
    g_act[(size_t)tok*HH + tid] = o;
}

// ------------------------------ launcher -----------------------------------
extern "C" void kernel_launch(void* const* d_in, const int* in_sizes, int n_in,
                              void* d_out, int out_size){
    const float* z     = (const float*)d_in[0];
    const float* Winit = (const float*)d_in[1];
    const float* binit = (const float*)d_in[2];
    const float* emb   = (const float*)d_in[3];
    const float* Wih0  = (const float*)d_in[4];
    const float* Whh0  = (const float*)d_in[5];
    const float* bih0  = (const float*)d_in[6];
    const float* bhh0  = (const float*)d_in[7];
    const float* Wih1  = (const float*)d_in[8];
    const float* Whh1  = (const float*)d_in[9];
    const float* bih1  = (const float*)d_in[10];
    const float* bhh1  = (const float*)d_in[11];
    const float* lng   = (const float*)d_in[12];
    const float* lnb   = (const float*)d_in[13];
    const float* Wout  = (const float*)d_in[14];
    const float* bout  = (const float*)d_in[15];
    float* out = (float*)d_out;

    cudaFuncSetAttribute(k_mma_gemm, cudaFuncAttributeMaxDynamicSharedMemorySize, GSM);

    k_transpose<<<dim3(8,24), dim3(32,8)>>>(Whh0, 0);
    k_transpose<<<dim3(8,24), dim3(32,8)>>>(Whh1, 1);
    k_init_h0<<<BB, HH>>>(z, Winit, binit);
    k_gx0<<<3, HH>>>(emb, Wih0, bih0);

    // GRU layer 0
    for (int t = 0; t < TT; t++)
        k_gru_step<<<dim3(4,32), 256>>>(0, t, bhh0);

    // gx1 = y0 @ Wih1^T + bih1 via HMMA (split-bf16)
    k_splitA<<<NTOK*64/256, 256>>>(0);
    k_splitB<<<NPAD*64/256, 256>>>(Wih1, 3*HH);
    k_mma_gemm<<<dim3(6, NTOK/128), 256, GSM>>>(bih1, nullptr, 1, 3*HH);

    // GRU layer 1
    for (int t = 0; t < TT; t++)
        k_gru_step<<<dim3(4,32), 256>>>(1, t, bhh1);

    k_ln_elu<<<NTOK, HH>>>(lng, lnb);

    // logits = act @ Wout^T + bout via HMMA (split-bf16)
    k_splitA<<<NTOK*64/256, 256>>>(1);
    k_splitB<<<NPAD*64/256, 256>>>(Wout, PP);
    k_mma_gemm<<<dim3(NPAD/128, NTOK/128), 256, GSM>>>(bout, out, 0, PP);
}